// round 15
// baseline (speedup 1.0000x reference)
#include <cuda_runtime.h>
#include <math.h>
#include <stdint.h>

#define BSZ   2
#define CF    128
#define NTOT  13824      // 24^3
#define MTOT  512        // 8^3
#define NHEAD 4
#define DHEAD 64
#define INNER 256
#define SCALE 0.125f     // 64^-0.5
#define FEAT_OUT_ELEMS 3538944   // 2*128*13824
#define KSPLIT 9
#define KLEN   1536      // 13824/9

// ------------------ scratch (device globals; no allocs) ------------------
__device__ __align__(16) float g_t1   [BSZ*CF*NTOT];            // dwconv1 out (tf32 bits)
__device__ __align__(16) float g_q    [BSZ*NHEAD*NTOT*DHEAD];   // feat_q (tf32 bits)
__device__ __align__(16) float g_fv   [BSZ*NHEAD*NTOT*DHEAD];   // feat_v (tf32 bits)
__device__ __align__(16) float g_mq   [BSZ*NHEAD*MTOT*DHEAD];   // map_q  (tf32 bits)
__device__ __align__(16) float g_mv   [BSZ*NHEAD*MTOT*DHEAD];   // map_v  (tf32 bits)
__device__ __align__(16) float g_attnout[BSZ*INNER*NTOT];       // feat attn out (fp32)
__device__ __align__(16) float g_dw2  [BSZ*INNER*NTOT];         // dwconv2 out (tf32 bits)
__device__ __align__(16) float g_monum[BSZ*NHEAD*MTOT*DHEAD];
__device__ __align__(16) float g_colsum[BSZ*NHEAD*MTOT];

// ------------------ tf32 mma helpers ------------------
__device__ __forceinline__ uint32_t f2t(float x){
    uint32_t r; asm("cvt.rna.tf32.f32 %0,%1;":"=r"(r):"f"(x)); return r;
}
__device__ __forceinline__ float f2tf(float x){ return __uint_as_float(f2t(x)); }
__device__ __forceinline__ float4 f2tf4(float4 v){
    v.x = f2tf(v.x); v.y = f2tf(v.y); v.z = f2tf(v.z); v.w = f2tf(v.w); return v;
}

__device__ __forceinline__ void mma8(float* c, const uint32_t* a, const uint32_t* b){
    asm volatile("mma.sync.aligned.m16n8k8.row.col.f32.tf32.tf32.f32 "
        "{%0,%1,%2,%3},{%4,%5,%6,%7},{%8,%9},{%0,%1,%2,%3};"
        : "+f"(c[0]),"+f"(c[1]),"+f"(c[2]),"+f"(c[3])
        : "r"(a[0]),"r"(a[1]),"r"(a[2]),"r"(a[3]),"r"(b[0]),"r"(b[1]));
}

// ------------------ cp.async helpers ------------------
__device__ __forceinline__ void cpa16(void* smem, const void* g){
    uint32_t s = (uint32_t)__cvta_generic_to_shared(smem);
    asm volatile("cp.async.ca.shared.global [%0], [%1], 16;" :: "r"(s), "l"(g));
}
#define CPA_COMMIT() asm volatile("cp.async.commit_group;")
#define CPA_WAIT0()  asm volatile("cp.async.wait_group 0;" ::: "memory")
#define CPA_WAIT1()  asm volatile("cp.async.wait_group 1;" ::: "memory")
#define CPA_WAIT2()  asm volatile("cp.async.wait_group 2;" ::: "memory")

// ------------------ depthwise 3x3x3, SAME, x-vectorized; output tf32-rounded
__device__ __forceinline__ void dw_body_v4(const float* __restrict__ in,
                                           const float* __restrict__ w,
                                           float* __restrict__ out, int C)
{
    __shared__ float ws[27];
    int t = threadIdx.x;
    int c = blockIdx.y, b = blockIdx.z;
    if (t < 27) ws[t] = w[c * 27 + t];
    __syncthreads();
    int idx = blockIdx.x * 256 + t;          // over 24*24*6 = 3456
    if (idx >= 3456) return;
    int x4 = (idx % 6) * 4;
    int y  = (idx / 6) % 24;
    int z  = idx / 144;
    const float* ip = in + ((size_t)(b * C + c)) * NTOT;
    float acc0 = 0.f, acc1 = 0.f, acc2 = 0.f, acc3 = 0.f;
    #pragma unroll
    for (int dz = -1; dz <= 1; dz++) {
        int zz = z + dz; if (zz < 0 || zz >= 24) continue;
        #pragma unroll
        for (int dy = -1; dy <= 1; dy++) {
            int yy = y + dy; if (yy < 0 || yy >= 24) continue;
            const float* row = ip + (zz * 24 + yy) * 24;
            float4 mid = *(const float4*)(row + x4);
            float left  = (x4 > 0)      ? row[x4 - 1] : 0.f;
            float right = (x4 + 4 < 24) ? row[x4 + 4] : 0.f;
            const float* wr = ws + (dz + 1) * 9 + (dy + 1) * 3;
            float w0 = wr[0], w1 = wr[1], w2 = wr[2];
            acc0 += w0 * left  + w1 * mid.x + w2 * mid.y;
            acc1 += w0 * mid.x + w1 * mid.y + w2 * mid.z;
            acc2 += w0 * mid.y + w1 * mid.z + w2 * mid.w;
            acc3 += w0 * mid.z + w1 * mid.w + w2 * right;
        }
    }
    float4 o = f2tf4(make_float4(acc0, acc1, acc2, acc3));
    *(float4*)(out + ((size_t)(b * C + c)) * NTOT + (z * 24 + y) * 24 + x4) = o;
}

__global__ void k_dwconv1(const float* __restrict__ feat, const float* __restrict__ w)
{   dw_body_v4(feat, w, g_t1, CF); }

__global__ void k_dwconv2(const float* __restrict__ w)
{   dw_body_v4(g_attnout, w, g_dw2, INNER); }

// ------------------ zero accumulators ------------------
__global__ void k_zero()
{
    int flat = blockIdx.x * 256 + threadIdx.x;     // 65536 threads
    float4 z4 = make_float4(0.f, 0.f, 0.f, 0.f);
    *(float4*)&g_monum[(size_t)flat * 4] = z4;
    if (flat < BSZ * NHEAD * MTOT) g_colsum[flat] = 0.f;
}

// ------------------ pointwise qv GEMM: M-tile 128, N-tile 64 ---------------
// warps 4m x 2n; B double-buffered cp.async; A via register staging.
// epilogue: two 64-o halves staged through Bs, d-run float4 stores.
__global__ __launch_bounds__(256) void k_pw_qv(const float* __restrict__ A)
{
    __shared__ float As[128*36];     // [m][k]
    __shared__ float Bs[2*32*72];    // [k][n] double buffer; also epilogue scratch
    int t = threadIdx.x, w = t >> 5, l = t & 31, g = l >> 2, q4 = l & 3;
    int bn = blockIdx.x * 64, bo = blockIdx.y * 128, b = blockIdx.z;
    int wm = (w >> 1) * 32, wn = (w & 1) * 32;
    float C[2][4][4] = {};
    const float* Xb = g_t1 + (size_t)b * CF * NTOT;

    // prologue: A(0) regs + B(0) cp.async
    float4 Ar[4];
    #pragma unroll
    for (int j = 0; j < 4; j++) {
        int idx = t + j * 256; int m = idx >> 3, k4 = idx & 7;
        Ar[j] = *(const float4*)&A[(bo + m)*128 + k4*4];
    }
    #pragma unroll
    for (int i = 0; i < 2; i++) {
        int idx = t + i * 256; int k = idx >> 4, n4 = idx & 15;
        cpa16(&Bs[k*72 + n4*4], &Xb[(size_t)k*NTOT + bn + n4*4]);
    }
    CPA_COMMIT();
    #pragma unroll
    for (int j = 0; j < 4; j++) {
        int idx = t + j * 256; int m = idx >> 3, k4 = idx & 7;
        *(float4*)&As[m*36 + k4*4] = f2tf4(Ar[j]);
    }
    CPA_WAIT0();
    __syncthreads();

    for (int it = 0; it < 4; it++) {
        int boff = (it & 1) * 2304;
        if (it < 3) {
            int kc = (it + 1) * 32;
            #pragma unroll
            for (int j = 0; j < 4; j++) {
                int idx = t + j * 256; int m = idx >> 3, k4 = idx & 7;
                Ar[j] = *(const float4*)&A[(bo + m)*128 + kc + k4*4];
            }
            int bn2 = ((it + 1) & 1) * 2304;
            #pragma unroll
            for (int i = 0; i < 2; i++) {
                int idx = t + i * 256; int k = idx >> 4, n4 = idx & 15;
                cpa16(&Bs[bn2 + k*72 + n4*4], &Xb[(size_t)(kc + k)*NTOT + bn + n4*4]);
            }
            CPA_COMMIT();
        }
        #pragma unroll
        for (int kk = 0; kk < 4; kk++) {
            uint32_t a[2][4], bb[4][2];
            #pragma unroll
            for (int mi = 0; mi < 2; mi++) {
                const float* ap = &As[(wm + mi*16 + g)*36 + kk*8 + q4];
                a[mi][0] = __float_as_uint(ap[0]);
                a[mi][1] = __float_as_uint(ap[8*36]);
                a[mi][2] = __float_as_uint(ap[4]);
                a[mi][3] = __float_as_uint(ap[8*36+4]);
            }
            #pragma unroll
            for (int ni = 0; ni < 4; ni++) {
                const float* bp = &Bs[boff + (kk*8 + q4)*72 + wn + ni*8 + g];
                bb[ni][0] = __float_as_uint(bp[0]);
                bb[ni][1] = __float_as_uint(bp[4*72]);
            }
            #pragma unroll
            for (int mi = 0; mi < 2; mi++)
                #pragma unroll
                for (int ni = 0; ni < 4; ni++) mma8(C[mi][ni], a[mi], bb[ni]);
        }
        __syncthreads();
        if (it < 3) {
            #pragma unroll
            for (int j = 0; j < 4; j++) {
                int idx = t + j * 256; int m = idx >> 3, k4 = idx & 7;
                *(float4*)&As[m*36 + k4*4] = f2tf4(Ar[j]);
            }
        }
        CPA_WAIT0();
        __syncthreads();
    }
    // ---- epilogue: two 64-o halves, staged [o][n] pitch 68 in Bs scratch ----
    float* Ct = Bs;   // 64*68 = 4352 <= 4608
    #pragma unroll
    for (int half = 0; half < 2; half++) {
        __syncthreads();
        if ((wm >> 6) == half) {
            int wml = wm & 63;
            #pragma unroll
            for (int mi = 0; mi < 2; mi++)
                #pragma unroll
                for (int ni = 0; ni < 4; ni++)
                    #pragma unroll
                    for (int cc = 0; cc < 4; cc++) {
                        int ol = wml + mi*16 + g + (cc >> 1)*8;
                        int nl = wn + ni*8 + 2*q4 + (cc & 1);
                        Ct[ol*68 + nl] = f2tf(C[mi][ni][cc]);
                    }
        }
        __syncthreads();
        int bo2 = bo + half*64;
        float* dst = (bo2 < 256) ? g_q : g_fv;
        int dbase = (bo2 & 255) >> 2;
        #pragma unroll
        for (int i = 0; i < 4; i++) {
            int idx = t + i * 256;             // < 1024
            int dq = idx & 3;
            int h  = (idx >> 2) & 3;
            int n  = idx >> 4;                 // 0..63
            float4 v;
            v.x = Ct[((dq*4+0)*4 + h)*68 + n];
            v.y = Ct[((dq*4+1)*4 + h)*68 + n];
            v.z = Ct[((dq*4+2)*4 + h)*68 + n];
            v.w = Ct[((dq*4+3)*4 + h)*68 + n];
            *(float4*)&dst[((size_t)(b*4 + h)*NTOT + bn + n)*64 + dbase + dq*4] = v;
        }
    }
}

// ------------------ map qv ------------------
__global__ __launch_bounds__(256) void k_map_qv(const float* __restrict__ w,
                                                const float* __restrict__ smap)
{
    __shared__ float Ws[32*68];
    __shared__ float Bs[64*132];
    int t = threadIdx.x;
    int bo = blockIdx.x * 32, b = blockIdx.y;
    int ol = (t >> 5) * 4;
    int ml = (t & 31) * 4;
    #pragma unroll
    for (int i = 0; i < 2; i++) {
        int idx = t + i * 256; int o = idx >> 4, c4 = idx & 15;
        *(float4*)&Ws[o*68 + c4*4] = *(const float4*)&w[(bo + o)*64 + c4*4];
    }
    for (int mc = 0; mc < 512; mc += 128) {
        __syncthreads();
        #pragma unroll
        for (int i = 0; i < 8; i++) {
            int idx = t + i * 256; int c = idx >> 5, m4 = idx & 31;
            *(float4*)&Bs[c*132 + m4*4] =
                *(const float4*)&smap[((size_t)(b*64 + c))*512 + mc + m4*4];
        }
        __syncthreads();
        float acc[4][4] = {};
        #pragma unroll 8
        for (int c = 0; c < 64; c++) {
            float4 bv = *(const float4*)&Bs[c*132 + ml];
            #pragma unroll
            for (int oi = 0; oi < 4; oi++) {
                float wv = Ws[(ol + oi)*68 + c];
                acc[oi][0] += wv * bv.x; acc[oi][1] += wv * bv.y;
                acc[oi][2] += wv * bv.z; acc[oi][3] += wv * bv.w;
            }
        }
        #pragma unroll
        for (int oi = 0; oi < 4; oi++) {
            int oo = bo + ol + oi;
            float* dst; int oc;
            if (oo < 256) { dst = g_mq; oc = oo; } else { dst = g_mv; oc = oo - 256; }
            size_t base = ((size_t)(b*4 + (oc & 3))*512 + mc + ml)*64 + (oc >> 2);
            dst[base]       = f2tf(acc[oi][0]);
            dst[base + 64]  = f2tf(acc[oi][1]);
            dst[base + 128] = f2tf(acc[oi][2]);
            dst[base + 192] = f2tf(acc[oi][3]);
        }
    }
}

// ------------------ attention pass 1: 2-sync pipelined flash block ---------
__global__ __launch_bounds__(256, 2) void k_attn1()
{
    __shared__ float MQd[2*32*68];
    __shared__ float MVd[32*72];
    __shared__ float Es[128*36];
    __shared__ float srs[128];
    int t = threadIdx.x, w = t >> 5, l = t & 31, g = l >> 2, q4 = l & 3;
    int bh = blockIdx.y, b = bh >> 2, h = bh & 3;
    int nb = blockIdx.x * 128;
    int wn  = (w >> 1) * 32;
    int wsm = (w & 1) * 16;
    int wd  = (w & 1) * 32;

    if (t < 128) srs[t] = 0.f;
    const float* Qb  = g_q  + ((size_t)bh*NTOT + nb) * 64;
    const float* MQg = g_mq + (size_t)bh * MTOT * 64;
    const float* MVg = g_mv + (size_t)bh * MTOT * 64;

    #pragma unroll
    for (int i = 0; i < 2; i++) {
        int idx = t + i*256; int m = idx >> 4, d4 = idx & 15;
        cpa16(&MQd[m*68 + d4*4], MQg + (size_t)m*64 + d4*4);
    }
    CPA_COMMIT();
    #pragma unroll
    for (int i = 0; i < 2; i++) {
        int idx = t + i*256; int m = idx >> 4, d4 = idx & 15;
        cpa16(&MVd[m*72 + d4*4], MVg + (size_t)m*64 + d4*4);
    }
    CPA_COMMIT();
    #pragma unroll
    for (int i = 0; i < 2; i++) {
        int idx = t + i*256; int m = idx >> 4, d4 = idx & 15;
        cpa16(&MQd[2176 + m*68 + d4*4], MQg + 2048 + (size_t)m*64 + d4*4);
    }
    CPA_COMMIT();

    uint32_t QF[8][2][4];
    for (int p = 0; p < 4; p++) {
        __syncthreads();
        #pragma unroll
        for (int i = 0; i < 2; i++) {
            int idx = t + i*256; int n = idx >> 4, d4 = idx & 15;
            *(float4*)&Es[n*68 + d4*4] = *(const float4*)&Qb[(size_t)(p*32 + n)*64 + d4*4];
        }
        __syncthreads();
        if ((w >> 1) == p) {
            #pragma unroll
            for (int kk = 0; kk < 8; kk++)
                #pragma unroll
                for (int mi = 0; mi < 2; mi++) {
                    const float* ap = &Es[(mi*16 + g)*68 + kk*8 + q4];
                    QF[kk][mi][0] = __float_as_uint(ap[0]);
                    QF[kk][mi][1] = __float_as_uint(ap[8*68]);
                    QF[kk][mi][2] = __float_as_uint(ap[4]);
                    QF[kk][mi][3] = __float_as_uint(ap[8*68+4]);
                }
        }
    }
    CPA_WAIT2();
    __syncthreads();

    float OF[2][4][4] = {};
    float rs[2][2] = {};

    for (int mc = 0; mc < 16; mc++) {
        int mqo = (mc & 1) * 2176;
        float Cs[2][2][4] = {};
        #pragma unroll
        for (int kk = 0; kk < 8; kk++) {
            uint32_t bb[2][2];
            #pragma unroll
            for (int ni = 0; ni < 2; ni++) {
                const float* bp = &MQd[mqo + (wsm + ni*8 + g)*68 + kk*8 + q4];
                bb[ni][0] = __float_as_uint(bp[0]);
                bb[ni][1] = __float_as_uint(bp[4]);
            }
            #pragma unroll
            for (int mi = 0; mi < 2; mi++)
                #pragma unroll
                for (int ni = 0; ni < 2; ni++) mma8(Cs[mi][ni], QF[kk][mi], bb[ni]);
        }
        #pragma unroll
        for (int mi = 0; mi < 2; mi++)
            #pragma unroll
            for (int ni = 0; ni < 2; ni++)
                #pragma unroll
                for (int cc = 0; cc < 4; cc++) {
                    float e = __expf(Cs[mi][ni][cc] * SCALE);
                    rs[mi][cc >> 1] += e;
                    Es[(wn + mi*16 + (cc>>1)*8 + g)*36 + wsm + ni*8 + 2*q4 + (cc&1)] = f2tf(e);
                }
        if (mc == 15) CPA_WAIT0(); else CPA_WAIT1();
        __syncthreads();
        #pragma unroll
        for (int kk = 0; kk < 4; kk++) {
            uint32_t a[2][4], bb[4][2];
            #pragma unroll
            for (int mi = 0; mi < 2; mi++) {
                const float* ap = &Es[(wn + mi*16 + g)*36 + kk*8 + q4];
                a[mi][0] = __float_as_uint(ap[0]);
                a[mi][1] = __float_as_uint(ap[8*36]);
                a[mi][2] = __float_as_uint(ap[4]);
                a[mi][3] = __float_as_uint(ap[8*36+4]);
            }
            #pragma unroll
            for (int ni = 0; ni < 4; ni++) {
                const float* bp = &MVd[(kk*8 + q4)*72 + wd + ni*8 + g];
                bb[ni][0] = __float_as_uint(bp[0]);
                bb[ni][1] = __float_as_uint(bp[4*72]);
            }
            #pragma unroll
            for (int mi = 0; mi < 2; mi++)
                #pragma unroll
                for (int ni = 0; ni < 4; ni++) mma8(OF[mi][ni], a[mi], bb[ni]);
        }
        __syncthreads();
        if (mc < 15) {
            size_t go = (size_t)(mc + 1) * 32 * 64;
            #pragma unroll
            for (int i = 0; i < 2; i++) {
                int idx = t + i*256; int m = idx >> 4, d4 = idx & 15;
                cpa16(&MVd[m*72 + d4*4], MVg + go + (size_t)m*64 + d4*4);
            }
            CPA_COMMIT();
            if (mc < 14) {
                int mqn = (mc & 1) * 2176;
                size_t go2 = (size_t)(mc + 2) * 32 * 64;
                #pragma unroll
                for (int i = 0; i < 2; i++) {
                    int idx = t + i*256; int m = idx >> 4, d4 = idx & 15;
                    cpa16(&MQd[mqn + m*68 + d4*4], MQg + go2 + (size_t)m*64 + d4*4);
                }
                CPA_COMMIT();
                CPA_WAIT2();
            } else {
                CPA_WAIT1();
            }
            __syncthreads();
        }
    }
    #pragma unroll
    for (int mi = 0; mi < 2; mi++)
        #pragma unroll
        for (int gh = 0; gh < 2; gh++) {
            float v = rs[mi][gh];
            v += __shfl_xor_sync(0xFFFFFFFFu, v, 1);
            v += __shfl_xor_sync(0xFFFFFFFFu, v, 2);
            if (q4 == 0) atomicAdd(&srs[wn + mi*16 + gh*8 + g], v);
        }
    __syncthreads();
    float* ao = g_attnout + (size_t)b * INNER * NTOT + nb;
    #pragma unroll
    for (int mi = 0; mi < 2; mi++) {
        int n0 = wn + mi*16 + g;
        float inv0 = 1.f / srs[n0];
        float inv1 = 1.f / srs[n0 + 8];
        #pragma unroll
        for (int ni = 0; ni < 4; ni++) {
            int d0 = wd + ni*8 + 2*q4;
            ao[(size_t)(4*d0 + h)*NTOT + n0]         = OF[mi][ni][0] * inv0;
            ao[(size_t)(4*(d0+1) + h)*NTOT + n0]     = OF[mi][ni][1] * inv0;
            ao[(size_t)(4*d0 + h)*NTOT + n0 + 8]     = OF[mi][ni][2] * inv1;
            ao[(size_t)(4*(d0+1) + h)*NTOT + n0 + 8] = OF[mi][ni][3] * inv1;
        }
    }
}

// ------------------ attention pass 2: 2-sync pipelined recompute-E ---------
__global__ __launch_bounds__(256, 2) void k_attn2()
{
    __shared__ float Qs[2*32*68];
    __shared__ float Vs[32*72];
    __shared__ float Es[128*36];
    __shared__ float scs[128];
    int t = threadIdx.x, w = t >> 5, l = t & 31, g = l >> 2, q4 = l & 3;
    int bh = blockIdx.z; int mtile = blockIdx.y * 128; int nb = blockIdx.x * KLEN;
    int wm = (w >> 1) * 32, wsn = (w & 1) * 16, wd = (w & 1) * 32;
    const float* Qb = g_q  + (size_t)bh * NTOT * 64;
    const float* Vb = g_fv + (size_t)bh * NTOT * 64;
    if (t < 128) scs[t] = 0.f;

    #pragma unroll
    for (int i = 0; i < 2; i++) {
        int idx = t + i*256; int n = idx >> 4, d4 = idx & 15;
        cpa16(&Qs[n*68 + d4*4], Qb + (size_t)(nb + n)*64 + d4*4);
    }
    CPA_COMMIT();
    #pragma unroll
    for (int i = 0; i < 2; i++) {
        int idx = t + i*256; int n = idx >> 4, d4 = idx & 15;
        cpa16(&Vs[n*72 + d4*4], Vb + (size_t)(nb + n)*64 + d4*4);
    }
    CPA_COMMIT();
    #pragma unroll
    for (int i = 0; i < 2; i++) {
        int idx = t + i*256; int n = idx >> 4, d4 = idx & 15;
        cpa16(&Qs[2176 + n*68 + d4*4], Qb + (size_t)(nb + 32 + n)*64 + d4*4);
    }
    CPA_COMMIT();

    uint32_t AF[8][2][4];
    const float* MQb = g_mq + ((size_t)bh * MTOT + mtile) * 64;
    #pragma unroll
    for (int kk = 0; kk < 8; kk++)
        #pragma unroll
        for (int mi = 0; mi < 2; mi++) {
            const float* p = MQb + (wm + mi*16 + g)*64 + kk*8 + q4;
            AF[kk][mi][0] = __float_as_uint(p[0]);
            AF[kk][mi][1] = __float_as_uint(p[8*64]);
            AF[kk][mi][2] = __float_as_uint(p[4]);
            AF[kk][mi][3] = __float_as_uint(p[8*64+4]);
        }
    float C[2][4][4] = {};
    float cs[2][2] = {};
    CPA_WAIT2();
    __syncthreads();

    for (int ci = 0; ci < 48; ci++) {
        int qo = (ci & 1) * 2176;
        float Cs[2][2][4] = {};
        #pragma unroll
        for (int kk = 0; kk < 8; kk++) {
            uint32_t bb[2][2];
            #pragma unroll
            for (int ni = 0; ni < 2; ni++) {
                const float* bp = &Qs[qo + (wsn + ni*8 + g)*68 + kk*8 + q4];
                bb[ni][0] = __float_as_uint(bp[0]);
                bb[ni][1] = __float_as_uint(bp[4]);
            }
            #pragma unroll
            for (int mi = 0; mi < 2; mi++)
                #pragma unroll
                for (int ni = 0; ni < 2; ni++) mma8(Cs[mi][ni], AF[kk][mi], bb[ni]);
        }
        #pragma unroll
        for (int mi = 0; mi < 2; mi++)
            #pragma unroll
            for (int ni = 0; ni < 2; ni++)
                #pragma unroll
                for (int cc = 0; cc < 4; cc++) {
                    float e = __expf(Cs[mi][ni][cc] * SCALE);
                    cs[mi][cc >> 1] += e;
                    Es[(wm + mi*16 + (cc>>1)*8 + g)*36 + wsn + ni*8 + 2*q4 + (cc&1)] = f2tf(e);
                }
        if (ci == 47) CPA_WAIT0(); else CPA_WAIT1();
        __syncthreads();
        #pragma unroll
        for (int kk = 0; kk < 4; kk++) {
            uint32_t a[2][4], bb[4][2];
            #pragma unroll
            for (int mi = 0; mi < 2; mi++) {
                const float* ap = &Es[(wm + mi*16 + g)*36 + kk*8 + q4];
                a[mi][0] = __float_as_uint(ap[0]);
                a[mi][1] = __float_as_uint(ap[8*36]);
                a[mi][2] = __float_as_uint(ap[4]);
                a[mi][3] = __float_as_uint(ap[8*36+4]);
            }
            #pragma unroll
            for (int ni = 0; ni < 4; ni++) {
                const float* bp = &Vs[(kk*8 + q4)*72 + wd + ni*8 + g];
                bb[ni][0] = __float_as_uint(bp[0]);
                bb[ni][1] = __float_as_uint(bp[4*72]);
            }
            #pragma unroll
            for (int mi = 0; mi < 2; mi++)
                #pragma unroll
                for (int ni = 0; ni < 4; ni++) mma8(C[mi][ni], a[mi], bb[ni]);
        }
        __syncthreads();
        if (ci < 47) {
            size_t base = (size_t)(nb + (ci + 1) * 32);
            #pragma unroll
            for (int i = 0; i < 2; i++) {
                int idx = t + i*256; int n = idx >> 4, d4 = idx & 15;
                cpa16(&Vs[n*72 + d4*4], Vb + (base + n)*64 + d4*4);
            }
            CPA_COMMIT();
            if (ci < 46) {
                int qn = (ci & 1) * 2176;
                size_t b2 = (size_t)(nb + (ci + 2) * 32);
                #pragma unroll
                for (int i = 0; i < 2; i++) {
                    int idx = t + i*256; int n = idx >> 4, d4 = idx & 15;
                    cpa16(&Qs[qn + n*68 + d4*4], Qb + (b2 + n)*64 + d4*4);
                }
                CPA_COMMIT();
                CPA_WAIT2();
            } else {
                CPA_WAIT1();
            }
            __syncthreads();
        }
    }
    #pragma unroll
    for (int mi = 0; mi < 2; mi++)
        #pragma unroll
        for (int gh = 0; gh < 2; gh++) {
            float v = cs[mi][gh];
            v += __shfl_xor_sync(0xFFFFFFFFu, v, 1);
            v += __shfl_xor_sync(0xFFFFFFFFu, v, 2);
            if (q4 == 0) atomicAdd(&scs[wm + mi*16 + gh*8 + g], v);
        }
    __syncthreads();
    if (t < 128) atomicAdd(&g_colsum[(size_t)bh*MTOT + mtile + t], scs[t]);
    #pragma unroll
    for (int mi = 0; mi < 2; mi++)
        #pragma unroll
        for (int ni = 0; ni < 4; ni++)
            #pragma unroll
            for (int cc = 0; cc < 4; cc++) {
                int m = mtile + wm + mi*16 + g + (cc >> 1)*8;
                int d = wd + ni*8 + 2*q4 + (cc & 1);
                atomicAdd(&g_monum[((size_t)bh*MTOT + m)*64 + d], C[mi][ni][cc]);
            }
}

// ------------------ finalize map_out (float4 over d) ------------------
__global__ void k_mapout(const float* __restrict__ w, float* __restrict__ outp)
{
    int gid = blockIdx.x * 256 + threadIdx.x;
    int m = gid & 511;
    int o = (gid >> 9) & 63;
    int b = gid >> 15;
    float inv[4];
    #pragma unroll
    for (int hh = 0; hh < 4; hh++)
        inv[hh] = 1.f / g_colsum[(size_t)(b * 4 + hh) * 512 + m];
    const float* wo = w + o * 256;
    float s = 0.f;
    #pragma unroll 4
    for (int d4 = 0; d4 < 16; d4++) {
        #pragma unroll
        for (int hh = 0; hh < 4; hh++) {
            float4 mv = *(const float4*)&g_monum[((size_t)(b*4 + hh)*512 + m)*64 + d4*4];
            s += (wo[16*d4 + hh]      * mv.x +
                  wo[16*d4 + 4 + hh]  * mv.y +
                  wo[16*d4 + 8 + hh]  * mv.z +
                  wo[16*d4 + 12 + hh] * mv.w) * inv[hh];
        }
    }
    outp[(size_t)FEAT_OUT_ELEMS + ((size_t)(b * 64 + o)) * 512 + m] = s;
}

// ------------------ pointwise out GEMM: full M=128, N-tile 64 --------------
__global__ __launch_bounds__(256) void k_pw_out(const float* __restrict__ A,
                                                float* __restrict__ outp)
{
    __shared__ float As[128*36];
    __shared__ float Bs[2*32*72];
    int t = threadIdx.x, w = t >> 5, l = t & 31, g = l >> 2, q4 = l & 3;
    int bn = blockIdx.x * 64, b = blockIdx.y;
    int wm = (w >> 1) * 32, wn = (w & 1) * 32;
    float C[2][4][4] = {};
    const float* Xb = g_dw2 + (size_t)b * INNER * NTOT;

    float4 Ar[4];
    #pragma unroll
    for (int j = 0; j < 4; j++) {
        int idx = t + j * 256; int m = idx >> 3, k4 = idx & 7;
        Ar[j] = *(const float4*)&A[m*256 + k4*4];
    }
    #pragma unroll
    for (int i = 0; i < 2; i++) {
        int idx = t + i * 256; int k = idx >> 4, n4 = idx & 15;
        cpa16(&Bs[k*72 + n4*4], &Xb[(size_t)k*NTOT + bn + n4*4]);
    }
    CPA_COMMIT();
    #pragma unroll
    for (int j = 0; j < 4; j++) {
        int idx = t + j * 256; int m = idx >> 3, k4 = idx & 7;
        *(float4*)&As[m*36 + k4*4] = f2tf4(Ar[j]);
    }
    CPA_WAIT0();
    __syncthreads();

    for (int it = 0; it < 8; it++) {
        int boff = (it & 1) * 2304;
        if (it < 7) {
            int kc = (it + 1) * 32;
            #pragma unroll
            for (int j = 0; j < 4; j++) {
                int idx = t + j * 256; int m = idx >> 3, k4 = idx & 7;
                Ar[j] = *(const float4*)&A[m*256 + kc + k4*4];
            }
            int bn2 = ((it + 1) & 1) * 2304;
            #pragma unroll
            for (int i = 0; i < 2; i++) {
                int idx = t + i * 256; int k = idx >> 4, n4 = idx & 15;
                cpa16(&Bs[bn2 + k*72 + n4*4], &Xb[(size_t)(kc + k)*NTOT + bn + n4*4]);
            }
            CPA_COMMIT();
        }
        #pragma unroll
        for (int kk = 0; kk < 4; kk++) {
            uint32_t a[2][4], bb[4][2];
            #pragma unroll
            for (int mi = 0; mi < 2; mi++) {
                const float* ap = &As[(wm + mi*16 + g)*36 + kk*8 + q4];
                a[mi][0] = __float_as_uint(ap[0]);
                a[mi][1] = __float_as_uint(ap[8*36]);
                a[mi][2] = __float_as_uint(ap[4]);
                a[mi][3] = __float_as_uint(ap[8*36+4]);
            }
            #pragma unroll
            for (int ni = 0; ni < 4; ni++) {
                const float* bp = &Bs[boff + (kk*8 + q4)*72 + wn + ni*8 + g];
                bb[ni][0] = __float_as_uint(bp[0]);
                bb[ni][1] = __float_as_uint(bp[4*72]);
            }
            #pragma unroll
            for (int mi = 0; mi < 2; mi++)
                #pragma unroll
                for (int ni = 0; ni < 4; ni++) mma8(C[mi][ni], a[mi], bb[ni]);
        }
        __syncthreads();
        if (it < 7) {
            #pragma unroll
            for (int j = 0; j < 4; j++) {
                int idx = t + j * 256; int m = idx >> 3, k4 = idx & 7;
                *(float4*)&As[m*36 + k4*4] = f2tf4(Ar[j]);
            }
        }
        CPA_WAIT0();
        __syncthreads();
    }
    #pragma unroll
    for (int mi = 0; mi < 2; mi++)
        #pragma unroll
        for (int ni = 0; ni < 4; ni++)
            #pragma unroll
            for (int cc = 0; cc < 4; cc++) {
                int o = wm + mi*16 + g + (cc >> 1)*8;
                int n = bn + wn + ni*8 + 2*q4 + (cc & 1);
                outp[((size_t)(b * 128 + o)) * NTOT + n] = C[mi][ni][cc];
            }
}

// ------------------ launch ------------------
extern "C" void kernel_launch(void* const* d_in, const int* in_sizes, int n_in,
                              void* d_out, int out_size)
{
    const float* feat    = (const float*)d_in[0];
    const float* smap    = (const float*)d_in[1];
    const float* fqv_dw  = (const float*)d_in[2];
    const float* fqv_pw  = (const float*)d_in[3];
    const float* fout_dw = (const float*)d_in[4];
    const float* fout_pw = (const float*)d_in[5];
    const float* mqv_w   = (const float*)d_in[6];
    const float* mout_w  = (const float*)d_in[7];
    float* outp = (float*)d_out;

    k_map_qv <<<dim3(16, 2), 256>>>(mqv_w, smap);
    k_dwconv1<<<dim3(14, 128, 2), 256>>>(feat, fqv_dw);
    k_zero   <<<256, 256>>>();
    k_pw_qv  <<<dim3(216, 4, 2), 256>>>(fqv_pw);        // launch #4 -> ncu window
    k_attn1  <<<dim3(108, 8), 256>>>();
    k_attn2  <<<dim3(KSPLIT, 4, 8), 256>>>();
    k_dwconv2<<<dim3(14, 256, 2), 256>>>(fout_dw);
    k_mapout <<<256, 256>>>(mout_w, outp);
    k_pw_out <<<dim3(216, 2), 256>>>(fout_pw, outp);
}

// round 16
// speedup vs baseline: 1.0163x; 1.0163x over previous
#include <cuda_runtime.h>
#include <math.h>
#include <stdint.h>

#define BSZ   2
#define CF    128
#define NTOT  13824      // 24^3
#define MTOT  512        // 8^3
#define NHEAD 4
#define DHEAD 64
#define INNER 256
#define SCALE 0.125f     // 64^-0.5
#define FEAT_OUT_ELEMS 3538944   // 2*128*13824
#define KSPLIT 9
#define KLEN   1536      // 13824/9

// ------------------ scratch (device globals; no allocs) ------------------
__device__ __align__(16) float g_t1   [BSZ*CF*NTOT];            // dwconv1 out (tf32 bits)
__device__ __align__(16) float g_q    [BSZ*NHEAD*NTOT*DHEAD];   // feat_q (tf32 bits)
__device__ __align__(16) float g_fv   [BSZ*NHEAD*NTOT*DHEAD];   // feat_v (tf32 bits)
__device__ __align__(16) float g_mq   [BSZ*NHEAD*MTOT*DHEAD];   // map_q  (tf32 bits)
__device__ __align__(16) float g_mv   [BSZ*NHEAD*MTOT*DHEAD];   // map_v  (tf32 bits)
__device__ __align__(16) float g_attnout[BSZ*INNER*NTOT];       // feat attn out (fp32)
__device__ __align__(16) float g_dw2  [BSZ*INNER*NTOT];         // dwconv2 out (tf32 bits)
__device__ __align__(16) float g_monum[BSZ*NHEAD*MTOT*DHEAD];
__device__ __align__(16) float g_colsum[BSZ*NHEAD*MTOT];

// ------------------ tf32 mma helpers ------------------
__device__ __forceinline__ uint32_t f2t(float x){
    uint32_t r; asm("cvt.rna.tf32.f32 %0,%1;":"=r"(r):"f"(x)); return r;
}
__device__ __forceinline__ float f2tf(float x){ return __uint_as_float(f2t(x)); }
__device__ __forceinline__ float4 f2tf4(float4 v){
    v.x = f2tf(v.x); v.y = f2tf(v.y); v.z = f2tf(v.z); v.w = f2tf(v.w); return v;
}

__device__ __forceinline__ void mma8(float* c, const uint32_t* a, const uint32_t* b){
    asm volatile("mma.sync.aligned.m16n8k8.row.col.f32.tf32.tf32.f32 "
        "{%0,%1,%2,%3},{%4,%5,%6,%7},{%8,%9},{%0,%1,%2,%3};"
        : "+f"(c[0]),"+f"(c[1]),"+f"(c[2]),"+f"(c[3])
        : "r"(a[0]),"r"(a[1]),"r"(a[2]),"r"(a[3]),"r"(b[0]),"r"(b[1]));
}

// ldmatrix x4: A-fragment (m16k8 tf32). Per-lane row address:
// row = base_row + (l&15), col = base_col + (l>>4)*4.  r0..r3 = a0..a3.
__device__ __forceinline__ void ldsm4(uint32_t* r, const float* p){
    uint32_t s = (uint32_t)__cvta_generic_to_shared(p);
    asm volatile("ldmatrix.sync.aligned.m8n8.x4.shared.b16 {%0,%1,%2,%3}, [%4];"
        : "=r"(r[0]),"=r"(r[1]),"=r"(r[2]),"=r"(r[3]) : "r"(s));
}

// ------------------ cp.async helpers ------------------
__device__ __forceinline__ void cpa16(void* smem, const void* g){
    uint32_t s = (uint32_t)__cvta_generic_to_shared(smem);
    asm volatile("cp.async.ca.shared.global [%0], [%1], 16;" :: "r"(s), "l"(g));
}
#define CPA_COMMIT() asm volatile("cp.async.commit_group;")
#define CPA_WAIT0()  asm volatile("cp.async.wait_group 0;" ::: "memory")
#define CPA_WAIT1()  asm volatile("cp.async.wait_group 1;" ::: "memory")
#define CPA_WAIT2()  asm volatile("cp.async.wait_group 2;" ::: "memory")

// ------------------ depthwise 3x3x3, SAME, x-vectorized; output tf32-rounded
__device__ __forceinline__ void dw_body_v4(const float* __restrict__ in,
                                           const float* __restrict__ w,
                                           float* __restrict__ out, int C)
{
    __shared__ float ws[27];
    int t = threadIdx.x;
    int c = blockIdx.y, b = blockIdx.z;
    if (t < 27) ws[t] = w[c * 27 + t];
    __syncthreads();
    int idx = blockIdx.x * 256 + t;          // over 24*24*6 = 3456
    if (idx >= 3456) return;
    int x4 = (idx % 6) * 4;
    int y  = (idx / 6) % 24;
    int z  = idx / 144;
    const float* ip = in + ((size_t)(b * C + c)) * NTOT;
    float acc0 = 0.f, acc1 = 0.f, acc2 = 0.f, acc3 = 0.f;
    #pragma unroll
    for (int dz = -1; dz <= 1; dz++) {
        int zz = z + dz; if (zz < 0 || zz >= 24) continue;
        #pragma unroll
        for (int dy = -1; dy <= 1; dy++) {
            int yy = y + dy; if (yy < 0 || yy >= 24) continue;
            const float* row = ip + (zz * 24 + yy) * 24;
            float4 mid = *(const float4*)(row + x4);
            float left  = (x4 > 0)      ? row[x4 - 1] : 0.f;
            float right = (x4 + 4 < 24) ? row[x4 + 4] : 0.f;
            const float* wr = ws + (dz + 1) * 9 + (dy + 1) * 3;
            float w0 = wr[0], w1 = wr[1], w2 = wr[2];
            acc0 += w0 * left  + w1 * mid.x + w2 * mid.y;
            acc1 += w0 * mid.x + w1 * mid.y + w2 * mid.z;
            acc2 += w0 * mid.y + w1 * mid.z + w2 * mid.w;
            acc3 += w0 * mid.z + w1 * mid.w + w2 * right;
        }
    }
    float4 o = f2tf4(make_float4(acc0, acc1, acc2, acc3));
    *(float4*)(out + ((size_t)(b * C + c)) * NTOT + (z * 24 + y) * 24 + x4) = o;
}

__global__ void k_dwconv1(const float* __restrict__ feat, const float* __restrict__ w)
{   dw_body_v4(feat, w, g_t1, CF); }

__global__ void k_dwconv2(const float* __restrict__ w)
{   dw_body_v4(g_attnout, w, g_dw2, INNER); }

// ------------------ zero accumulators ------------------
__global__ void k_zero()
{
    int flat = blockIdx.x * 256 + threadIdx.x;     // 65536 threads
    float4 z4 = make_float4(0.f, 0.f, 0.f, 0.f);
    *(float4*)&g_monum[(size_t)flat * 4] = z4;
    if (flat < BSZ * NHEAD * MTOT) g_colsum[flat] = 0.f;
}

// ------------------ pointwise qv GEMM (R13 tiling + ldmatrix A) ------------
__global__ __launch_bounds__(256) void k_pw_qv(const float* __restrict__ A)
{
    __shared__ __align__(16) float As[64*36];
    __shared__ __align__(16) float Bs[2*32*136];   // also epilogue staging
    int t = threadIdx.x, w = t >> 5, l = t & 31, g = l >> 2, q4 = l & 3;
    int lrow = l & 15, lcol = (l >> 4) * 4;
    int bn = blockIdx.x * 128, bo = blockIdx.y * 64, b = blockIdx.z;
    int wm = (w >> 2) * 32, wn = (w & 3) * 32;
    int am = t >> 3, ak4 = t & 7;
    int am2 = (t + 256) >> 3;
    float C[2][4][4] = {};
    const float* Xb = g_t1 + (size_t)b * CF * NTOT;

    float4 Ar0 = *(const float4*)&A[(bo + am)*128 + ak4*4];
    float4 Ar1 = *(const float4*)&A[(bo + am2)*128 + ak4*4];
    #pragma unroll
    for (int i = 0; i < 4; i++) {
        int idx = t + i * 256; int k = idx >> 5, n4 = idx & 31;
        cpa16(&Bs[k*136 + n4*4], &Xb[(size_t)k*NTOT + bn + n4*4]);
    }
    CPA_COMMIT();
    *(float4*)&As[am*36 + ak4*4]  = f2tf4(Ar0);
    *(float4*)&As[am2*36 + ak4*4] = f2tf4(Ar1);
    CPA_WAIT0();
    __syncthreads();

    for (int it = 0; it < 4; it++) {
        int boff = (it & 1) * 4352;
        if (it < 3) {
            int kc = (it + 1) * 32;
            Ar0 = *(const float4*)&A[(bo + am)*128 + kc + ak4*4];
            Ar1 = *(const float4*)&A[(bo + am2)*128 + kc + ak4*4];
            int bn2 = ((it + 1) & 1) * 4352;
            #pragma unroll
            for (int i = 0; i < 4; i++) {
                int idx = t + i * 256; int k = idx >> 5, n4 = idx & 31;
                cpa16(&Bs[bn2 + k*136 + n4*4], &Xb[(size_t)(kc + k)*NTOT + bn + n4*4]);
            }
            CPA_COMMIT();
        }
        #pragma unroll
        for (int kk = 0; kk < 4; kk++) {
            uint32_t a[2][4], bb[4][2];
            #pragma unroll
            for (int mi = 0; mi < 2; mi++)
                ldsm4(a[mi], &As[(wm + mi*16 + lrow)*36 + kk*8 + lcol]);
            #pragma unroll
            for (int ni = 0; ni < 4; ni++) {
                const float* bp = &Bs[boff + (kk*8 + q4)*136 + wn + ni*8 + g];
                bb[ni][0] = __float_as_uint(bp[0]);
                bb[ni][1] = __float_as_uint(bp[4*136]);
            }
            #pragma unroll
            for (int mi = 0; mi < 2; mi++)
                #pragma unroll
                for (int ni = 0; ni < 4; ni++) mma8(C[mi][ni], a[mi], bb[ni]);
        }
        __syncthreads();
        if (it < 3) {
            *(float4*)&As[am*36 + ak4*4]  = f2tf4(Ar0);
            *(float4*)&As[am2*36 + ak4*4] = f2tf4(Ar1);
        }
        CPA_WAIT0();
        __syncthreads();
    }
    // ---- epilogue: stage C [o][n] pitch 133, d-run float4 stores
    float* Ct = Bs;   // 64*133 = 8512 <= 8704
    #pragma unroll
    for (int mi = 0; mi < 2; mi++)
        #pragma unroll
        for (int ni = 0; ni < 4; ni++)
            #pragma unroll
            for (int cc = 0; cc < 4; cc++) {
                int ol = wm + mi*16 + g + (cc >> 1)*8;
                int nl = wn + ni*8 + 2*q4 + (cc & 1);
                Ct[ol*133 + nl] = f2tf(C[mi][ni][cc]);
            }
    __syncthreads();
    float* dst = (bo < 256) ? g_q : g_fv;
    int dbase = (bo & 255) >> 2;
    #pragma unroll
    for (int i = 0; i < 8; i++) {
        int idx = t + i * 256;             // < 2048
        int dq = idx & 3;
        int h  = (idx >> 2) & 3;
        int n  = idx >> 4;                 // 0..127
        float4 v;
        v.x = Ct[((dq*4+0)*4 + h)*133 + n];
        v.y = Ct[((dq*4+1)*4 + h)*133 + n];
        v.z = Ct[((dq*4+2)*4 + h)*133 + n];
        v.w = Ct[((dq*4+3)*4 + h)*133 + n];
        *(float4*)&dst[((size_t)(b*4 + h)*NTOT + bn + n)*64 + dbase + dq*4] = v;
    }
}

// ------------------ map qv ------------------
__global__ __launch_bounds__(256) void k_map_qv(const float* __restrict__ w,
                                                const float* __restrict__ smap)
{
    __shared__ float Ws[32*68];
    __shared__ float Bs[64*132];
    int t = threadIdx.x;
    int bo = blockIdx.x * 32, b = blockIdx.y;
    int ol = (t >> 5) * 4;
    int ml = (t & 31) * 4;
    #pragma unroll
    for (int i = 0; i < 2; i++) {
        int idx = t + i * 256; int o = idx >> 4, c4 = idx & 15;
        *(float4*)&Ws[o*68 + c4*4] = *(const float4*)&w[(bo + o)*64 + c4*4];
    }
    for (int mc = 0; mc < 512; mc += 128) {
        __syncthreads();
        #pragma unroll
        for (int i = 0; i < 8; i++) {
            int idx = t + i * 256; int c = idx >> 5, m4 = idx & 31;
            *(float4*)&Bs[c*132 + m4*4] =
                *(const float4*)&smap[((size_t)(b*64 + c))*512 + mc + m4*4];
        }
        __syncthreads();
        float acc[4][4] = {};
        #pragma unroll 8
        for (int c = 0; c < 64; c++) {
            float4 bv = *(const float4*)&Bs[c*132 + ml];
            #pragma unroll
            for (int oi = 0; oi < 4; oi++) {
                float wv = Ws[(ol + oi)*68 + c];
                acc[oi][0] += wv * bv.x; acc[oi][1] += wv * bv.y;
                acc[oi][2] += wv * bv.z; acc[oi][3] += wv * bv.w;
            }
        }
        #pragma unroll
        for (int oi = 0; oi < 4; oi++) {
            int oo = bo + ol + oi;
            float* dst; int oc;
            if (oo < 256) { dst = g_mq; oc = oo; } else { dst = g_mv; oc = oo - 256; }
            size_t base = ((size_t)(b*4 + (oc & 3))*512 + mc + ml)*64 + (oc >> 2);
            dst[base]       = f2tf(acc[oi][0]);
            dst[base + 64]  = f2tf(acc[oi][1]);
            dst[base + 128] = f2tf(acc[oi][2]);
            dst[base + 192] = f2tf(acc[oi][3]);
        }
    }
}

// ------------------ attention pass 1: 2-sync pipeline + ldmatrix E --------
__global__ __launch_bounds__(256, 2) void k_attn1()
{
    __shared__ __align__(16) float MQd[2*32*68];
    __shared__ __align__(16) float MVd[32*72];
    __shared__ __align__(16) float Es[128*36];
    __shared__ float srs[128];
    int t = threadIdx.x, w = t >> 5, l = t & 31, g = l >> 2, q4 = l & 3;
    int lrow = l & 15, lcol = (l >> 4) * 4;
    int bh = blockIdx.y, b = bh >> 2, h = bh & 3;
    int nb = blockIdx.x * 128;
    int wn  = (w >> 1) * 32;
    int wsm = (w & 1) * 16;
    int wd  = (w & 1) * 32;

    if (t < 128) srs[t] = 0.f;
    const float* Qb  = g_q  + ((size_t)bh*NTOT + nb) * 64;
    const float* MQg = g_mq + (size_t)bh * MTOT * 64;
    const float* MVg = g_mv + (size_t)bh * MTOT * 64;

    #pragma unroll
    for (int i = 0; i < 2; i++) {
        int idx = t + i*256; int m = idx >> 4, d4 = idx & 15;
        cpa16(&MQd[m*68 + d4*4], MQg + (size_t)m*64 + d4*4);
    }
    CPA_COMMIT();
    #pragma unroll
    for (int i = 0; i < 2; i++) {
        int idx = t + i*256; int m = idx >> 4, d4 = idx & 15;
        cpa16(&MVd[m*72 + d4*4], MVg + (size_t)m*64 + d4*4);
    }
    CPA_COMMIT();
    #pragma unroll
    for (int i = 0; i < 2; i++) {
        int idx = t + i*256; int m = idx >> 4, d4 = idx & 15;
        cpa16(&MQd[2176 + m*68 + d4*4], MQg + 2048 + (size_t)m*64 + d4*4);
    }
    CPA_COMMIT();

    uint32_t QF[8][2][4];
    for (int p = 0; p < 4; p++) {
        __syncthreads();
        #pragma unroll
        for (int i = 0; i < 2; i++) {
            int idx = t + i*256; int n = idx >> 4, d4 = idx & 15;
            *(float4*)&Es[n*68 + d4*4] = *(const float4*)&Qb[(size_t)(p*32 + n)*64 + d4*4];
        }
        __syncthreads();
        if ((w >> 1) == p) {
            #pragma unroll
            for (int kk = 0; kk < 8; kk++)
                #pragma unroll
                for (int mi = 0; mi < 2; mi++) {
                    const float* ap = &Es[(mi*16 + g)*68 + kk*8 + q4];
                    QF[kk][mi][0] = __float_as_uint(ap[0]);
                    QF[kk][mi][1] = __float_as_uint(ap[8*68]);
                    QF[kk][mi][2] = __float_as_uint(ap[4]);
                    QF[kk][mi][3] = __float_as_uint(ap[8*68+4]);
                }
        }
    }
    CPA_WAIT2();
    __syncthreads();

    float OF[2][4][4] = {};
    float rs[2][2] = {};

    for (int mc = 0; mc < 16; mc++) {
        int mqo = (mc & 1) * 2176;
        float Cs[2][2][4] = {};
        #pragma unroll
        for (int kk = 0; kk < 8; kk++) {
            uint32_t bb[2][2];
            #pragma unroll
            for (int ni = 0; ni < 2; ni++) {
                const float* bp = &MQd[mqo + (wsm + ni*8 + g)*68 + kk*8 + q4];
                bb[ni][0] = __float_as_uint(bp[0]);
                bb[ni][1] = __float_as_uint(bp[4]);
            }
            #pragma unroll
            for (int mi = 0; mi < 2; mi++)
                #pragma unroll
                for (int ni = 0; ni < 2; ni++) mma8(Cs[mi][ni], QF[kk][mi], bb[ni]);
        }
        #pragma unroll
        for (int mi = 0; mi < 2; mi++)
            #pragma unroll
            for (int ni = 0; ni < 2; ni++)
                #pragma unroll
                for (int cc = 0; cc < 4; cc++) {
                    float e = __expf(Cs[mi][ni][cc] * SCALE);
                    rs[mi][cc >> 1] += e;
                    Es[(wn + mi*16 + (cc>>1)*8 + g)*36 + wsm + ni*8 + 2*q4 + (cc&1)] = f2tf(e);
                }
        if (mc == 15) CPA_WAIT0(); else CPA_WAIT1();
        __syncthreads();
        #pragma unroll
        for (int kk = 0; kk < 4; kk++) {
            uint32_t a[2][4], bb[4][2];
            #pragma unroll
            for (int mi = 0; mi < 2; mi++)
                ldsm4(a[mi], &Es[(wn + mi*16 + lrow)*36 + kk*8 + lcol]);
            #pragma unroll
            for (int ni = 0; ni < 4; ni++) {
                const float* bp = &MVd[(kk*8 + q4)*72 + wd + ni*8 + g];
                bb[ni][0] = __float_as_uint(bp[0]);
                bb[ni][1] = __float_as_uint(bp[4*72]);
            }
            #pragma unroll
            for (int mi = 0; mi < 2; mi++)
                #pragma unroll
                for (int ni = 0; ni < 4; ni++) mma8(OF[mi][ni], a[mi], bb[ni]);
        }
        __syncthreads();
        if (mc < 15) {
            size_t go = (size_t)(mc + 1) * 32 * 64;
            #pragma unroll
            for (int i = 0; i < 2; i++) {
                int idx = t + i*256; int m = idx >> 4, d4 = idx & 15;
                cpa16(&MVd[m*72 + d4*4], MVg + go + (size_t)m*64 + d4*4);
            }
            CPA_COMMIT();
            if (mc < 14) {
                int mqn = (mc & 1) * 2176;
                size_t go2 = (size_t)(mc + 2) * 32 * 64;
                #pragma unroll
                for (int i = 0; i < 2; i++) {
                    int idx = t + i*256; int m = idx >> 4, d4 = idx & 15;
                    cpa16(&MQd[mqn + m*68 + d4*4], MQg + go2 + (size_t)m*64 + d4*4);
                }
                CPA_COMMIT();
                CPA_WAIT2();
            } else {
                CPA_WAIT1();
            }
            __syncthreads();
        }
    }
    #pragma unroll
    for (int mi = 0; mi < 2; mi++)
        #pragma unroll
        for (int gh = 0; gh < 2; gh++) {
            float v = rs[mi][gh];
            v += __shfl_xor_sync(0xFFFFFFFFu, v, 1);
            v += __shfl_xor_sync(0xFFFFFFFFu, v, 2);
            if (q4 == 0) atomicAdd(&srs[wn + mi*16 + gh*8 + g], v);
        }
    __syncthreads();
    float* ao = g_attnout + (size_t)b * INNER * NTOT + nb;
    #pragma unroll
    for (int mi = 0; mi < 2; mi++) {
        int n0 = wn + mi*16 + g;
        float inv0 = 1.f / srs[n0];
        float inv1 = 1.f / srs[n0 + 8];
        #pragma unroll
        for (int ni = 0; ni < 4; ni++) {
            int d0 = wd + ni*8 + 2*q4;
            ao[(size_t)(4*d0 + h)*NTOT + n0]         = OF[mi][ni][0] * inv0;
            ao[(size_t)(4*(d0+1) + h)*NTOT + n0]     = OF[mi][ni][1] * inv0;
            ao[(size_t)(4*d0 + h)*NTOT + n0 + 8]     = OF[mi][ni][2] * inv1;
            ao[(size_t)(4*(d0+1) + h)*NTOT + n0 + 8] = OF[mi][ni][3] * inv1;
        }
    }
}

// ------------------ attention pass 2: 2-sync pipeline + ldmatrix E --------
__global__ __launch_bounds__(256, 2) void k_attn2()
{
    __shared__ __align__(16) float Qs[2*32*68];
    __shared__ __align__(16) float Vs[32*72];
    __shared__ __align__(16) float Es[128*36];
    __shared__ float scs[128];
    int t = threadIdx.x, w = t >> 5, l = t & 31, g = l >> 2, q4 = l & 3;
    int lrow = l & 15, lcol = (l >> 4) * 4;
    int bh = blockIdx.z; int mtile = blockIdx.y * 128; int nb = blockIdx.x * KLEN;
    int wm = (w >> 1) * 32, wsn = (w & 1) * 16, wd = (w & 1) * 32;
    const float* Qb = g_q  + (size_t)bh * NTOT * 64;
    const float* Vb = g_fv + (size_t)bh * NTOT * 64;
    if (t < 128) scs[t] = 0.f;

    #pragma unroll
    for (int i = 0; i < 2; i++) {
        int idx = t + i*256; int n = idx >> 4, d4 = idx & 15;
        cpa16(&Qs[n*68 + d4*4], Qb + (size_t)(nb + n)*64 + d4*4);
    }
    CPA_COMMIT();
    #pragma unroll
    for (int i = 0; i < 2; i++) {
        int idx = t + i*256; int n = idx >> 4, d4 = idx & 15;
        cpa16(&Vs[n*72 + d4*4], Vb + (size_t)(nb + n)*64 + d4*4);
    }
    CPA_COMMIT();
    #pragma unroll
    for (int i = 0; i < 2; i++) {
        int idx = t + i*256; int n = idx >> 4, d4 = idx & 15;
        cpa16(&Qs[2176 + n*68 + d4*4], Qb + (size_t)(nb + 32 + n)*64 + d4*4);
    }
    CPA_COMMIT();

    uint32_t AF[8][2][4];
    const float* MQb = g_mq + ((size_t)bh * MTOT + mtile) * 64;
    #pragma unroll
    for (int kk = 0; kk < 8; kk++)
        #pragma unroll
        for (int mi = 0; mi < 2; mi++) {
            const float* p = MQb + (wm + mi*16 + g)*64 + kk*8 + q4;
            AF[kk][mi][0] = __float_as_uint(p[0]);
            AF[kk][mi][1] = __float_as_uint(p[8*64]);
            AF[kk][mi][2] = __float_as_uint(p[4]);
            AF[kk][mi][3] = __float_as_uint(p[8*64+4]);
        }
    float C[2][4][4] = {};
    float cs[2][2] = {};
    CPA_WAIT2();
    __syncthreads();

    for (int ci = 0; ci < 48; ci++) {
        int qo = (ci & 1) * 2176;
        float Cs[2][2][4] = {};
        #pragma unroll
        for (int kk = 0; kk < 8; kk++) {
            uint32_t bb[2][2];
            #pragma unroll
            for (int ni = 0; ni < 2; ni++) {
                const float* bp = &Qs[qo + (wsn + ni*8 + g)*68 + kk*8 + q4];
                bb[ni][0] = __float_as_uint(bp[0]);
                bb[ni][1] = __float_as_uint(bp[4]);
            }
            #pragma unroll
            for (int mi = 0; mi < 2; mi++)
                #pragma unroll
                for (int ni = 0; ni < 2; ni++) mma8(Cs[mi][ni], AF[kk][mi], bb[ni]);
        }
        #pragma unroll
        for (int mi = 0; mi < 2; mi++)
            #pragma unroll
            for (int ni = 0; ni < 2; ni++)
                #pragma unroll
                for (int cc = 0; cc < 4; cc++) {
                    float e = __expf(Cs[mi][ni][cc] * SCALE);
                    cs[mi][cc >> 1] += e;
                    Es[(wm + mi*16 + (cc>>1)*8 + g)*36 + wsn + ni*8 + 2*q4 + (cc&1)] = f2tf(e);
                }
        if (ci == 47) CPA_WAIT0(); else CPA_WAIT1();
        __syncthreads();
        #pragma unroll
        for (int kk = 0; kk < 4; kk++) {
            uint32_t a[2][4], bb[4][2];
            #pragma unroll
            for (int mi = 0; mi < 2; mi++)
                ldsm4(a[mi], &Es[(wm + mi*16 + lrow)*36 + kk*8 + lcol]);
            #pragma unroll
            for (int ni = 0; ni < 4; ni++) {
                const float* bp = &Vs[(kk*8 + q4)*72 + wd + ni*8 + g];
                bb[ni][0] = __float_as_uint(bp[0]);
                bb[ni][1] = __float_as_uint(bp[4*72]);
            }
            #pragma unroll
            for (int mi = 0; mi < 2; mi++)
                #pragma unroll
                for (int ni = 0; ni < 4; ni++) mma8(C[mi][ni], a[mi], bb[ni]);
        }
        __syncthreads();
        if (ci < 47) {
            size_t base = (size_t)(nb + (ci + 1) * 32);
            #pragma unroll
            for (int i = 0; i < 2; i++) {
                int idx = t + i*256; int n = idx >> 4, d4 = idx & 15;
                cpa16(&Vs[n*72 + d4*4], Vb + (base + n)*64 + d4*4);
            }
            CPA_COMMIT();
            if (ci < 46) {
                int qn = (ci & 1) * 2176;
                size_t b2 = (size_t)(nb + (ci + 2) * 32);
                #pragma unroll
                for (int i = 0; i < 2; i++) {
                    int idx = t + i*256; int n = idx >> 4, d4 = idx & 15;
                    cpa16(&Qs[qn + n*68 + d4*4], Qb + (b2 + n)*64 + d4*4);
                }
                CPA_COMMIT();
                CPA_WAIT2();
            } else {
                CPA_WAIT1();
            }
            __syncthreads();
        }
    }
    #pragma unroll
    for (int mi = 0; mi < 2; mi++)
        #pragma unroll
        for (int gh = 0; gh < 2; gh++) {
            float v = cs[mi][gh];
            v += __shfl_xor_sync(0xFFFFFFFFu, v, 1);
            v += __shfl_xor_sync(0xFFFFFFFFu, v, 2);
            if (q4 == 0) atomicAdd(&scs[wm + mi*16 + gh*8 + g], v);
        }
    __syncthreads();
    if (t < 128) atomicAdd(&g_colsum[(size_t)bh*MTOT + mtile + t], scs[t]);
    #pragma unroll
    for (int mi = 0; mi < 2; mi++)
        #pragma unroll
        for (int ni = 0; ni < 4; ni++)
            #pragma unroll
            for (int cc = 0; cc < 4; cc++) {
                int m = mtile + wm + mi*16 + g + (cc >> 1)*8;
                int d = wd + ni*8 + 2*q4 + (cc & 1);
                atomicAdd(&g_monum[((size_t)bh*MTOT + m)*64 + d], C[mi][ni][cc]);
            }
}

// ------------------ finalize map_out (float4 over d) ------------------
__global__ void k_mapout(const float* __restrict__ w, float* __restrict__ outp)
{
    int gid = blockIdx.x * 256 + threadIdx.x;
    int m = gid & 511;
    int o = (gid >> 9) & 63;
    int b = gid >> 15;
    float inv[4];
    #pragma unroll
    for (int hh = 0; hh < 4; hh++)
        inv[hh] = 1.f / g_colsum[(size_t)(b * 4 + hh) * 512 + m];
    const float* wo = w + o * 256;
    float s = 0.f;
    #pragma unroll 4
    for (int d4 = 0; d4 < 16; d4++) {
        #pragma unroll
        for (int hh = 0; hh < 4; hh++) {
            float4 mv = *(const float4*)&g_monum[((size_t)(b*4 + hh)*512 + m)*64 + d4*4];
            s += (wo[16*d4 + hh]      * mv.x +
                  wo[16*d4 + 4 + hh]  * mv.y +
                  wo[16*d4 + 8 + hh]  * mv.z +
                  wo[16*d4 + 12 + hh] * mv.w) * inv[hh];
        }
    }
    outp[(size_t)FEAT_OUT_ELEMS + ((size_t)(b * 64 + o)) * 512 + m] = s;
}

// ------------------ pointwise out GEMM (R13 tiling + ldmatrix A) -----------
__global__ __launch_bounds__(256) void k_pw_out(const float* __restrict__ A,
                                                float* __restrict__ outp)
{
    __shared__ __align__(16) float As[64*36];
    __shared__ __align__(16) float Bs[2*32*136];
    int t = threadIdx.x, w = t >> 5, l = t & 31, g = l >> 2, q4 = l & 3;
    int lrow = l & 15, lcol = (l >> 4) * 4;
    int bn = blockIdx.x * 128, bo = blockIdx.y * 64, b = blockIdx.z;
    int wm = (w >> 2) * 32, wn = (w & 3) * 32;
    int am = t >> 3, ak4 = t & 7;
    int am2 = (t + 256) >> 3;
    float C[2][4][4] = {};
    const float* Xb = g_dw2 + (size_t)b * INNER * NTOT;

    float4 Ar0 = *(const float4*)&A[(bo + am)*256 + ak4*4];
    float4 Ar1 = *(const float4*)&A[(bo + am2)*256 + ak4*4];
    #pragma unroll
    for (int i = 0; i < 4; i++) {
        int idx = t + i * 256; int k = idx >> 5, n4 = idx & 31;
        cpa16(&Bs[k*136 + n4*4], &Xb[(size_t)k*NTOT + bn + n4*4]);
    }
    CPA_COMMIT();
    *(float4*)&As[am*36 + ak4*4]  = f2tf4(Ar0);
    *(float4*)&As[am2*36 + ak4*4] = f2tf4(Ar1);
    CPA_WAIT0();
    __syncthreads();

    for (int it = 0; it < 8; it++) {
        int boff = (it & 1) * 4352;
        if (it < 7) {
            int kc = (it + 1) * 32;
            Ar0 = *(const float4*)&A[(bo + am)*256 + kc + ak4*4];
            Ar1 = *(const float4*)&A[(bo + am2)*256 + kc + ak4*4];
            int bn2 = ((it + 1) & 1) * 4352;
            #pragma unroll
            for (int i = 0; i < 4; i++) {
                int idx = t + i * 256; int k = idx >> 5, n4 = idx & 31;
                cpa16(&Bs[bn2 + k*136 + n4*4], &Xb[(size_t)(kc + k)*NTOT + bn + n4*4]);
            }
            CPA_COMMIT();
        }
        #pragma unroll
        for (int kk = 0; kk < 4; kk++) {
            uint32_t a[2][4], bb[4][2];
            #pragma unroll
            for (int mi = 0; mi < 2; mi++)
                ldsm4(a[mi], &As[(wm + mi*16 + lrow)*36 + kk*8 + lcol]);
            #pragma unroll
            for (int ni = 0; ni < 4; ni++) {
                const float* bp = &Bs[boff + (kk*8 + q4)*136 + wn + ni*8 + g];
                bb[ni][0] = __float_as_uint(bp[0]);
                bb[ni][1] = __float_as_uint(bp[4*136]);
            }
            #pragma unroll
            for (int mi = 0; mi < 2; mi++)
                #pragma unroll
                for (int ni = 0; ni < 4; ni++) mma8(C[mi][ni], a[mi], bb[ni]);
        }
        __syncthreads();
        if (it < 7) {
            *(float4*)&As[am*36 + ak4*4]  = f2tf4(Ar0);
            *(float4*)&As[am2*36 + ak4*4] = f2tf4(Ar1);
        }
        CPA_WAIT0();
        __syncthreads();
    }
    #pragma unroll
    for (int mi = 0; mi < 2; mi++)
        #pragma unroll
        for (int ni = 0; ni < 4; ni++)
            #pragma unroll
            for (int cc = 0; cc < 4; cc++) {
                int o = bo + wm + mi*16 + g + (cc >> 1)*8;
                int n = bn + wn + ni*8 + 2*q4 + (cc & 1);
                outp[((size_t)(b * 128 + o)) * NTOT + n] = C[mi][ni][cc];
            }
}

// ------------------ launch ------------------
extern "C" void kernel_launch(void* const* d_in, const int* in_sizes, int n_in,
                              void* d_out, int out_size)
{
    const float* feat    = (const float*)d_in[0];
    const float* smap    = (const float*)d_in[1];
    const float* fqv_dw  = (const float*)d_in[2];
    const float* fqv_pw  = (const float*)d_in[3];
    const float* fout_dw = (const float*)d_in[4];
    const float* fout_pw = (const float*)d_in[5];
    const float* mqv_w   = (const float*)d_in[6];
    const float* mout_w  = (const float*)d_in[7];
    float* outp = (float*)d_out;

    k_map_qv <<<dim3(16, 2), 256>>>(mqv_w, smap);
    k_dwconv1<<<dim3(14, 128, 2), 256>>>(feat, fqv_dw);
    k_zero   <<<256, 256>>>();
    k_pw_qv  <<<dim3(108, 8, 2), 256>>>(fqv_pw);        // launch #4 -> ncu window
    k_attn1  <<<dim3(108, 8), 256>>>();
    k_attn2  <<<dim3(KSPLIT, 4, 8), 256>>>();
    k_dwconv2<<<dim3(14, 256, 2), 256>>>(fout_dw);
    k_mapout <<<256, 256>>>(mout_w, outp);
    k_pw_out <<<dim3(108, 2, 2), 256>>>(fout_pw, outp);
}